// round 2
// baseline (speedup 1.0000x reference)
#include <cuda_runtime.h>
#include <math.h>

#define BB 16
#define LL 2048
#define DD 64
#define TQ 64
#define TK 64
#define NTHREADS 128

// Fused attention: pass 1 = QK^T + masks + raw-score store + online softmax stats,
// pass 2 = normalize (write final attn) + P@V.
__global__ __launch_bounds__(NTHREADS)
void attn_fused_kernel(const float* __restrict__ qg,
                       const float* __restrict__ kg,
                       const float* __restrict__ vg,
                       const int* __restrict__ diag,
                       const int* __restrict__ maskb,
                       float* __restrict__ outp,
                       float* __restrict__ attn)
{
    __shared__ float SA[TQ][65];   // pass1: Q tile [q][d]; pass2: P tile [q][k]
    __shared__ float SB[TK][65];   // pass1: K tile [k][d]; pass2: V tile [k][d]

    const int b    = blockIdx.y;
    const int q0   = blockIdx.x * TQ;
    const int tid  = threadIdx.x;
    const int tcol = tid & 15;       // 0..15
    const int trow = tid >> 4;       // 0..7
    const int qr0  = trow * 8;       // 8 query rows per thread

    // ---- load Q tile (scaled by 1/temperature) ----
    const float* qptr = qg + ((size_t)b * LL + q0) * DD;
    #pragma unroll
    for (int it = 0; it < (TQ * DD / 4) / NTHREADS; ++it) {
        int i  = tid + it * NTHREADS;        // [0, 64*16)
        int r  = i >> 4;
        int c4 = (i & 15) << 2;
        float4 t = *reinterpret_cast<const float4*>(qptr + (size_t)r * DD + c4);
        SA[r][c4 + 0] = t.x * 0.125f;
        SA[r][c4 + 1] = t.y * 0.125f;
        SA[r][c4 + 2] = t.z * 0.125f;
        SA[r][c4 + 3] = t.w * 0.125f;
    }

    float m_run[8], l_run[8];
    #pragma unroll
    for (int i = 0; i < 8; ++i) { m_run[i] = -3.0e38f; l_run[i] = 0.0f; }

    // =========================== PASS 1 ===========================
    for (int kt = 0; kt < LL / TK; ++kt) {
        const int k0 = kt * TK;
        __syncthreads();   // previous chunk's SB consumption done
        const float* kptr = kg + ((size_t)b * LL + k0) * DD;
        #pragma unroll
        for (int it = 0; it < (TK * DD / 4) / NTHREADS; ++it) {
            int i  = tid + it * NTHREADS;
            int r  = i >> 4;
            int c4 = (i & 15) << 2;
            float4 t = *reinterpret_cast<const float4*>(kptr + (size_t)r * DD + c4);
            SB[r][c4 + 0] = t.x;
            SB[r][c4 + 1] = t.y;
            SB[r][c4 + 2] = t.z;
            SB[r][c4 + 3] = t.w;
        }
        __syncthreads();

        float acc[8][4];
        #pragma unroll
        for (int i = 0; i < 8; ++i)
            #pragma unroll
            for (int j = 0; j < 4; ++j) acc[i][j] = 0.0f;

        #pragma unroll 8
        for (int d = 0; d < DD; ++d) {
            float a[8], bv[4];
            #pragma unroll
            for (int i = 0; i < 8; ++i) a[i] = SA[qr0 + i][d];
            #pragma unroll
            for (int j = 0; j < 4; ++j) bv[j] = SB[tcol + 16 * j][d];
            #pragma unroll
            for (int i = 0; i < 8; ++i)
                #pragma unroll
                for (int j = 0; j < 4; ++j)
                    acc[i][j] = fmaf(a[i], bv[j], acc[i][j]);
        }

        // masks + raw-score store + online softmax statistics
        #pragma unroll
        for (int i = 0; i < 8; ++i) {
            const size_t rowbase = ((size_t)b * LL + (q0 + qr0 + i)) * LL + k0;
            float s[4];
            #pragma unroll
            for (int j = 0; j < 4; ++j) {
                int kk = tcol + 16 * j;
                float val = acc[i][j];
                if (maskb[rowbase + kk] != 0) val = -INFINITY;  // mask -> -inf
                if (diag[rowbase + kk] == 0)  val = -1.0e32f;   // diag==0 overrides
                s[j] = val;
                attn[rowbase + kk] = val;                       // raw masked score
            }
            float tmax = fmaxf(fmaxf(s[0], s[1]), fmaxf(s[2], s[3]));
            #pragma unroll
            for (int w = 1; w < 16; w <<= 1)
                tmax = fmaxf(tmax, __shfl_xor_sync(0xffffffffu, tmax, w));
            tmax = fmaxf(tmax, -3.0e38f);                       // keep finite (no NaN path)
            float mnew = fmaxf(m_run[i], tmax);
            float se = __expf(s[0] - mnew) + __expf(s[1] - mnew)
                     + __expf(s[2] - mnew) + __expf(s[3] - mnew);
            #pragma unroll
            for (int w = 1; w < 16; w <<= 1)
                se += __shfl_xor_sync(0xffffffffu, se, w);
            l_run[i] = l_run[i] * __expf(m_run[i] - mnew) + se;
            m_run[i] = mnew;
        }
    }

    // Final stats are replicated across the 16-lane subgroup; each thread
    // already holds them for exactly its own 8 rows.
    float rm[8], rinv[8];
    #pragma unroll
    for (int i = 0; i < 8; ++i) { rm[i] = m_run[i]; rinv[i] = 1.0f / l_run[i]; }

    float oacc[8][4];
    #pragma unroll
    for (int i = 0; i < 8; ++i)
        #pragma unroll
        for (int j = 0; j < 4; ++j) oacc[i][j] = 0.0f;

    // =========================== PASS 2 ===========================
    for (int kt = 0; kt < LL / TK; ++kt) {
        const int k0 = kt * TK;
        __syncthreads();   // previous chunk (or pass-1 tail) consumption done

        // V tile -> SB
        const float* vptr = vg + ((size_t)b * LL + k0) * DD;
        #pragma unroll
        for (int it = 0; it < (TK * DD / 4) / NTHREADS; ++it) {
            int i  = tid + it * NTHREADS;
            int r  = i >> 4;
            int c4 = (i & 15) << 2;
            float4 t = *reinterpret_cast<const float4*>(vptr + (size_t)r * DD + c4);
            SB[r][c4 + 0] = t.x;
            SB[r][c4 + 1] = t.y;
            SB[r][c4 + 2] = t.z;
            SB[r][c4 + 3] = t.w;
        }

        // normalize scores -> final attn + stage P tile in SA
        #pragma unroll
        for (int i = 0; i < 8; ++i) {
            const size_t rowbase = ((size_t)b * LL + (q0 + qr0 + i)) * LL + k0;
            #pragma unroll
            for (int j = 0; j < 4; ++j) {
                int kk = tcol + 16 * j;
                float sv = attn[rowbase + kk];         // same-thread RAW, ordered
                float p  = __expf(sv - rm[i]) * rinv[i];
                attn[rowbase + kk] = p;                // final softmax probs
                SA[qr0 + i][kk] = p;
            }
        }
        __syncthreads();

        // O += P @ V
        #pragma unroll 8
        for (int kk2 = 0; kk2 < TK; ++kk2) {
            float pv[8], vv[4];
            #pragma unroll
            for (int i = 0; i < 8; ++i) pv[i] = SA[qr0 + i][kk2];
            #pragma unroll
            for (int j = 0; j < 4; ++j) vv[j] = SB[kk2][tcol + 16 * j];
            #pragma unroll
            for (int i = 0; i < 8; ++i)
                #pragma unroll
                for (int j = 0; j < 4; ++j)
                    oacc[i][j] = fmaf(pv[i], vv[j], oacc[i][j]);
        }
    }

    // write output tile
    #pragma unroll
    for (int i = 0; i < 8; ++i) {
        const size_t obase = ((size_t)b * LL + (q0 + qr0 + i)) * DD;
        #pragma unroll
        for (int j = 0; j < 4; ++j)
            outp[obase + tcol + 16 * j] = oacc[i][j];
    }
}

extern "C" void kernel_launch(void* const* d_in, const int* in_sizes, int n_in,
                              void* d_out, int out_size)
{
    const float* q    = (const float*)d_in[0];
    const float* k    = (const float*)d_in[1];
    const float* v    = (const float*)d_in[2];
    const int*   diag = (const int*)d_in[3];
    const int*   mask = (const int*)d_in[4];   // jnp.bool_ marshalled as int32

    float* out  = (float*)d_out;                       // [B, L, D]
    float* attn = out + (size_t)BB * LL * DD;          // [B, L, L]

    dim3 grid(LL / TQ, BB);
    attn_fused_kernel<<<grid, NTHREADS>>>(q, k, v, diag, mask, out, attn);
}

// round 4
// speedup vs baseline: 2.2367x; 2.2367x over previous
#include <cuda_runtime.h>
#include <cuda_bf16.h>
#include <stdint.h>

#define BB 16
#define LLEN 2048
#define DD 64
#define TQ 128
#define NTH 256
#define STRIDE 144               // smem row stride in bytes (72 bf16, 16B-mult, conflict-free)

#define OFF_QH 0
#define OFF_QL (128 * STRIDE)
#define OFF_KH (2 * 128 * STRIDE)
#define OFF_KL (OFF_KH + 64 * STRIDE)
#define SMEM_TOTAL (OFF_KL + 64 * STRIDE)   // 55296 bytes
#define OFF_VH 0                 // pass2 V aliases Q region
#define OFF_VL (128 * STRIDE)

#define NEG_INF __int_as_float(0xff800000)

// ---------------- helpers ----------------
__device__ __forceinline__ uint32_t smem_u32(const void* p) {
    uint32_t a;
    asm("{ .reg .u64 t; cvta.to.shared.u64 t, %1; cvt.u32.u64 %0, t; }" : "=r"(a) : "l"(p));
    return a;
}
__device__ __forceinline__ void ldsm4(uint32_t a, uint32_t r[4]) {
    asm volatile("ldmatrix.sync.aligned.m8n8.x4.shared.b16 {%0,%1,%2,%3}, [%4];"
                 : "=r"(r[0]), "=r"(r[1]), "=r"(r[2]), "=r"(r[3]) : "r"(a));
}
__device__ __forceinline__ void ldsm4t(uint32_t a, uint32_t r[4]) {
    asm volatile("ldmatrix.sync.aligned.m8n8.x4.trans.shared.b16 {%0,%1,%2,%3}, [%4];"
                 : "=r"(r[0]), "=r"(r[1]), "=r"(r[2]), "=r"(r[3]) : "r"(a));
}
__device__ __forceinline__ void mma_bf16(float* d, const uint32_t* a, uint32_t b0, uint32_t b1) {
    asm volatile("mma.sync.aligned.m16n8k16.row.col.f32.bf16.bf16.f32 "
                 "{%0,%1,%2,%3}, {%4,%5,%6,%7}, {%8,%9}, {%0,%1,%2,%3};"
                 : "+f"(d[0]), "+f"(d[1]), "+f"(d[2]), "+f"(d[3])
                 : "r"(a[0]), "r"(a[1]), "r"(a[2]), "r"(a[3]), "r"(b0), "r"(b1));
}
__device__ __forceinline__ void split2(float a, float b, uint32_t& hi, uint32_t& lo) {
    __nv_bfloat16 ah = __float2bfloat16(a);
    __nv_bfloat16 bh = __float2bfloat16(b);
    float ar = a - __bfloat162float(ah);
    float br = b - __bfloat162float(bh);
    __nv_bfloat162 H; H.x = ah; H.y = bh;
    __nv_bfloat162 L; L.x = __float2bfloat16(ar); L.y = __float2bfloat16(br);
    hi = *reinterpret_cast<uint32_t*>(&H);
    lo = *reinterpret_cast<uint32_t*>(&L);
}

// rows x 64 fp32 (contiguous) -> bf16 hi/lo smem tiles with STRIDE-byte rows
template <int ROWS>
__device__ __forceinline__ void load_tile(const float* __restrict__ g,
                                          char* hi, char* lo, float scale, int tid) {
    #pragma unroll
    for (int it = 0; it < ROWS * 16 / NTH; ++it) {
        int idx = tid + it * NTH;                    // float4 index
        float4 t = reinterpret_cast<const float4*>(g)[idx];
        uint32_t h01, l01, h23, l23;
        split2(t.x * scale, t.y * scale, h01, l01);
        split2(t.z * scale, t.w * scale, h23, l23);
        int r  = idx >> 4;
        int c8 = (idx & 15) << 3;                    // byte offset within row
        *reinterpret_cast<uint2*>(hi + r * STRIDE + c8) = make_uint2(h01, h23);
        *reinterpret_cast<uint2*>(lo + r * STRIDE + c8) = make_uint2(l01, l23);
    }
}

__global__ __launch_bounds__(NTH, 2)
void attn_mma_kernel(const float* __restrict__ qg,
                     const float* __restrict__ kg,
                     const float* __restrict__ vg,
                     const int* __restrict__ diag,
                     const int* __restrict__ maskb,
                     float* __restrict__ outp,
                     float* __restrict__ attn)
{
    extern __shared__ __align__(16) char smem[];
    const int tid  = threadIdx.x;
    const int wid  = tid >> 5;
    const int lane = tid & 31;
    const int qt   = lane & 3;
    const int b    = blockIdx.y;
    const int q0   = blockIdx.x * TQ;

    const uint32_t sb = smem_u32(smem);

    // Q tile (pre-scaled by 1/temperature) -> QH/QL
    load_tile<128>(qg + ((size_t)b * LLEN + q0) * DD, smem + OFF_QH, smem + OFF_QL,
                   0.125f, tid);

    const int r0l = wid * 16 + (lane >> 2);          // this thread's row0 (row1 = +8)
    const size_t g0 = (size_t)b * LLEN + q0 + r0l;
    const int* m0p = maskb + g0 * LLEN;
    const int* m1p = m0p + (size_t)8 * LLEN;
    const int* d0p = diag + g0 * LLEN;
    const int* d1p = d0p + (size_t)8 * LLEN;
    float* a0p = attn + g0 * LLEN;
    float* a1p = a0p + (size_t)8 * LLEN;

    // ldmatrix per-lane address components
    const uint32_t aoff = (uint32_t)((wid * 16 + (lane & 7) + ((lane >> 3) & 1) * 8) * STRIDE
                                     + (lane >> 4) * 16);
    const uint32_t qh_a = sb + OFF_QH + aoff;
    const uint32_t ql_a = sb + OFF_QL + aoff;
    const uint32_t boff = (uint32_t)(((((lane >> 4) & 1) * 8) + (lane & 7)) * STRIDE
                                     + ((lane >> 3) & 1) * 16);
    const uint32_t kh_a = sb + OFF_KH + boff;
    const uint32_t kl_a = sb + OFF_KL + boff;
    const uint32_t voff = (uint32_t)(((((lane >> 3) & 1) * 8) + (lane & 7)) * STRIDE
                                     + ((lane >> 4) & 1) * 16);
    const uint32_t vh_a = sb + OFF_VH + voff;
    const uint32_t vl_a = sb + OFF_VL + voff;

    float m0 = -3.0e38f, m1 = -3.0e38f, l0 = 0.0f, l1 = 0.0f;

    // =========================== PASS 1: S = QK^T, masks, stats ===========================
    for (int kt = 0; kt < 32; ++kt) {
        const int k0 = kt * 64;
        __syncthreads();
        load_tile<64>(kg + ((size_t)b * LLEN + k0) * DD, smem + OFF_KH, smem + OFF_KL,
                      1.0f, tid);
        __syncthreads();

        float acc[8][4];
        #pragma unroll
        for (int nt = 0; nt < 8; ++nt)
            #pragma unroll
            for (int i = 0; i < 4; ++i) acc[nt][i] = 0.0f;

        #pragma unroll
        for (int kc = 0; kc < 4; ++kc) {
            uint32_t ah[4], al[4];
            ldsm4(qh_a + kc * 32, ah);
            ldsm4(ql_a + kc * 32, al);
            #pragma unroll
            for (int p = 0; p < 4; ++p) {
                uint32_t kh4[4], kl4[4];
                ldsm4(kh_a + p * 16 * STRIDE + kc * 32, kh4);
                ldsm4(kl_a + p * 16 * STRIDE + kc * 32, kl4);
                mma_bf16(acc[2 * p],     ah, kh4[0], kh4[1]);
                mma_bf16(acc[2 * p],     ah, kl4[0], kl4[1]);
                mma_bf16(acc[2 * p],     al, kh4[0], kh4[1]);
                mma_bf16(acc[2 * p + 1], ah, kh4[2], kh4[3]);
                mma_bf16(acc[2 * p + 1], ah, kl4[2], kl4[3]);
                mma_bf16(acc[2 * p + 1], al, kh4[2], kh4[3]);
            }
        }

        // masks + raw score store + tile max
        float t0 = -3.0e38f, t1 = -3.0e38f;
        #pragma unroll
        for (int nt = 0; nt < 8; ++nt) {
            const int cb = k0 + nt * 8 + qt * 2;
            int2 mm0 = *reinterpret_cast<const int2*>(m0p + cb);
            int2 dd0 = *reinterpret_cast<const int2*>(d0p + cb);
            int2 mm1 = *reinterpret_cast<const int2*>(m1p + cb);
            int2 dd1 = *reinterpret_cast<const int2*>(d1p + cb);
            float s0 = acc[nt][0], s1 = acc[nt][1], s2 = acc[nt][2], s3 = acc[nt][3];
            if (mm0.x) s0 = NEG_INF;  if (dd0.x == 0) s0 = -1.0e32f;
            if (mm0.y) s1 = NEG_INF;  if (dd0.y == 0) s1 = -1.0e32f;
            if (mm1.x) s2 = NEG_INF;  if (dd1.x == 0) s2 = -1.0e32f;
            if (mm1.y) s3 = NEG_INF;  if (dd1.y == 0) s3 = -1.0e32f;
            *reinterpret_cast<float2*>(a0p + cb) = make_float2(s0, s1);
            *reinterpret_cast<float2*>(a1p + cb) = make_float2(s2, s3);
            acc[nt][0] = s0; acc[nt][1] = s1; acc[nt][2] = s2; acc[nt][3] = s3;
            t0 = fmaxf(t0, fmaxf(s0, s1));
            t1 = fmaxf(t1, fmaxf(s2, s3));
        }
        t0 = fmaxf(t0, __shfl_xor_sync(0xffffffffu, t0, 1));
        t0 = fmaxf(t0, __shfl_xor_sync(0xffffffffu, t0, 2));
        t1 = fmaxf(t1, __shfl_xor_sync(0xffffffffu, t1, 1));
        t1 = fmaxf(t1, __shfl_xor_sync(0xffffffffu, t1, 2));
        const float mn0 = fmaxf(m0, t0);
        const float mn1 = fmaxf(m1, t1);
        float e0 = 0.0f, e1 = 0.0f;
        #pragma unroll
        for (int nt = 0; nt < 8; ++nt) {
            e0 += __expf(acc[nt][0] - mn0) + __expf(acc[nt][1] - mn0);
            e1 += __expf(acc[nt][2] - mn1) + __expf(acc[nt][3] - mn1);
        }
        e0 += __shfl_xor_sync(0xffffffffu, e0, 1);
        e0 += __shfl_xor_sync(0xffffffffu, e0, 2);
        e1 += __shfl_xor_sync(0xffffffffu, e1, 1);
        e1 += __shfl_xor_sync(0xffffffffu, e1, 2);
        l0 = l0 * __expf(m0 - mn0) + e0;  m0 = mn0;
        l1 = l1 * __expf(m1 - mn1) + e1;  m1 = mn1;
    }

    const float rinv0 = 1.0f / l0;
    const float rinv1 = 1.0f / l1;

    float oacc[8][4];
    #pragma unroll
    for (int nt = 0; nt < 8; ++nt)
        #pragma unroll
        for (int i = 0; i < 4; ++i) oacc[nt][i] = 0.0f;

    // =========================== PASS 2: attn probs + O = P V ===========================
    for (int kt = 0; kt < 16; ++kt) {
        const int k0 = kt * 128;
        __syncthreads();
        load_tile<128>(vg + ((size_t)b * LLEN + k0) * DD, smem + OFF_VH, smem + OFF_VL,
                       1.0f, tid);
        __syncthreads();

        #pragma unroll
        for (int kc = 0; kc < 8; ++kc) {
            const int cb = k0 + kc * 16 + qt * 2;
            float2 x0  = *reinterpret_cast<const float2*>(a0p + cb);
            float2 x0h = *reinterpret_cast<const float2*>(a0p + cb + 8);
            float2 x1  = *reinterpret_cast<const float2*>(a1p + cb);
            float2 x1h = *reinterpret_cast<const float2*>(a1p + cb + 8);
            float p00 = __expf(x0.x  - m0) * rinv0;
            float p01 = __expf(x0.y  - m0) * rinv0;
            float p02 = __expf(x0h.x - m0) * rinv0;
            float p03 = __expf(x0h.y - m0) * rinv0;
            float p10 = __expf(x1.x  - m1) * rinv1;
            float p11 = __expf(x1.y  - m1) * rinv1;
            float p12 = __expf(x1h.x - m1) * rinv1;
            float p13 = __expf(x1h.y - m1) * rinv1;
            *reinterpret_cast<float2*>(a0p + cb)     = make_float2(p00, p01);
            *reinterpret_cast<float2*>(a0p + cb + 8) = make_float2(p02, p03);
            *reinterpret_cast<float2*>(a1p + cb)     = make_float2(p10, p11);
            *reinterpret_cast<float2*>(a1p + cb + 8) = make_float2(p12, p13);

            uint32_t ah[4], al[4];
            split2(p00, p01, ah[0], al[0]);   // row0, k-lo
            split2(p10, p11, ah[1], al[1]);   // row1, k-lo
            split2(p02, p03, ah[2], al[2]);   // row0, k-hi
            split2(p12, p13, ah[3], al[3]);   // row1, k-hi

            #pragma unroll
            for (int p = 0; p < 4; ++p) {
                uint32_t vh4[4], vl4[4];
                ldsm4t(vh_a + kc * 16 * STRIDE + p * 32, vh4);
                ldsm4t(vl_a + kc * 16 * STRIDE + p * 32, vl4);
                mma_bf16(oacc[2 * p],     ah, vh4[0], vh4[1]);
                mma_bf16(oacc[2 * p],     ah, vl4[0], vl4[1]);
                mma_bf16(oacc[2 * p],     al, vh4[0], vh4[1]);
                mma_bf16(oacc[2 * p + 1], ah, vh4[2], vh4[3]);
                mma_bf16(oacc[2 * p + 1], ah, vl4[2], vl4[3]);
                mma_bf16(oacc[2 * p + 1], al, vh4[2], vh4[3]);
            }
        }
    }

    // ---- write output ----
    float* o0 = outp + g0 * DD;
    float* o1 = o0 + (size_t)8 * DD;
    #pragma unroll
    for (int nt = 0; nt < 8; ++nt) {
        const int cb = nt * 8 + qt * 2;
        *reinterpret_cast<float2*>(o0 + cb) = make_float2(oacc[nt][0], oacc[nt][1]);
        *reinterpret_cast<float2*>(o1 + cb) = make_float2(oacc[nt][2], oacc[nt][3]);
    }
}

extern "C" void kernel_launch(void* const* d_in, const int* in_sizes, int n_in,
                              void* d_out, int out_size)
{
    const float* q    = (const float*)d_in[0];
    const float* k    = (const float*)d_in[1];
    const float* v    = (const float*)d_in[2];
    const int*   diag = (const int*)d_in[3];
    const int*   mask = (const int*)d_in[4];

    float* out  = (float*)d_out;                     // [B, L, D]
    float* attn = out + (size_t)BB * LLEN * DD;      // [B, L, L]

    cudaFuncSetAttribute(attn_mma_kernel,
                         cudaFuncAttributeMaxDynamicSharedMemorySize, SMEM_TOTAL);
    dim3 grid(LLEN / TQ, BB);
    attn_mma_kernel<<<grid, NTH, SMEM_TOTAL>>>(q, k, v, diag, mask, out, attn);
}